// round 5
// baseline (speedup 1.0000x reference)
#include <cuda_runtime.h>
#include <cstdint>
#include <cstddef>

// ---------------- problem constants ----------------
#define TOTAL    65536          // B_GRAPHS * N_NODES
#define NGRAPH   16
#define NNODES   4096
#define INCH     256
#define HID      512
#define LN_EPS   1e-5f
#define QK_EPS   1e-6f
#define SPLITS   8              // for ksum partials
#define SK       4              // split-K for kv GEMM

// ---------------- GEMM tiling ----------------
#define BM 128
#define BN 256
#define BK 32
// A slot TR0: 128 rows x 36 floats = 18432 B ; A slot TR1: 32 x 136 = 17408 B
// B slot TR0: 256 rows x 36 floats = 36864 B ; B slot TR1: 32 x 264 = 33792 B
#define A_SLOT_BYTES 18432
#define B_SLOT_BYTES 36864
#define STAGE_BYTES (A_SLOT_BYTES + B_SLOT_BYTES)   // 55296
#define NSTAGE 3
#define SMEM_BYTES (NSTAGE * STAGE_BYTES)           // 165888

// epilogue modes
#define EPI_NONE 0
#define EPI_BIAS 1
#define EPI_ATT  2

// ---------------- scratch (device globals; no allocation) ----------------
__device__ float g_h  [(size_t)TOTAL * HID];
__device__ float g_q  [(size_t)TOTAL * HID];
__device__ float g_k  [(size_t)TOTAL * HID];
__device__ float g_v  [(size_t)TOTAL * HID];
__device__ float g_t  [(size_t)TOTAL * HID];
__device__ float g_xr [(size_t)TOTAL * INCH];
__device__ float g_wr [(size_t)(HID * INCH + 6 * HID * HID)];
__device__ float g_kvp [(size_t)SK * NGRAPH * HID * HID];
__device__ float g_kvs [(size_t)NGRAPH * HID * HID];
__device__ float g_ksp [(size_t)SPLITS * NGRAPH * HID];
__device__ float g_ks  [(size_t)NGRAPH * HID];
__device__ float g_den [(size_t)TOTAL];

// ---------------- helpers ----------------
__device__ __forceinline__ uint32_t smem_to_u32(const void* p) {
    uint32_t a;
    asm("{ .reg .u64 t; cvta.to.shared.u64 t, %1; cvt.u32.u64 %0, t; }" : "=r"(a) : "l"(p));
    return a;
}
__device__ __forceinline__ uint32_t f2tf32(float f) {
    uint32_t u;
    asm("cvt.rna.tf32.f32 %0, %1;" : "=r"(u) : "f"(f));
    return u;
}
__device__ __forceinline__ float roundtf(float f) { return __uint_as_float(f2tf32(f)); }

__device__ __forceinline__ void mma_tf32(float (&c)[4], const uint32_t (&a)[4],
                                         const uint32_t (&b)[2]) {
    asm volatile(
        "mma.sync.aligned.m16n8k8.row.col.f32.tf32.tf32.f32 "
        "{%0,%1,%2,%3}, {%4,%5,%6,%7}, {%8,%9}, {%0,%1,%2,%3};"
        : "+f"(c[0]), "+f"(c[1]), "+f"(c[2]), "+f"(c[3])
        : "r"(a[0]), "r"(a[1]), "r"(a[2]), "r"(a[3]), "r"(b[0]), "r"(b[1]));
}
__device__ __forceinline__ void ldsm_x4(uint32_t (&r)[4], uint32_t addr) {
    asm volatile("ldmatrix.sync.aligned.m8n8.x4.shared.b16 {%0,%1,%2,%3}, [%4];"
        : "=r"(r[0]), "=r"(r[1]), "=r"(r[2]), "=r"(r[3]) : "r"(addr));
}
__device__ __forceinline__ uint32_t lds32(uint32_t addr) {
    uint32_t v;
    asm volatile("ld.shared.b32 %0, [%1];" : "=r"(v) : "r"(addr));
    return v;
}
__device__ __forceinline__ void cpa16(uint32_t dst, const float* src) {
    asm volatile("cp.async.cg.shared.global [%0], [%1], 16;" :: "r"(dst), "l"(src) : "memory");
}
#define CP_COMMIT() asm volatile("cp.async.commit_group;" ::: "memory")

// ================= tf32 mma.sync GEMM, 128x256 tile, warp 64x64, 3-stage =================
// C[m0+i, n0+j] (+epilogue) = sum_k A(i,k) * B(j,k)
// TR==0: operand K-contiguous (slot S[row][k], stride 36, ldmatrix frags)
// TR==1: operand MN-contiguous (slot S[k][col], stride 136(A)/264(B), LDS.32 frags)
// MULTI: N spans 3 output buffers of width 512 (merged QKV); C/P1/P2 are q/k/v.
template <int TA, int TB, int EPI, int RND, int MULTI>
__global__ __launch_bounds__(256, 1)
void mm_tc(const float* __restrict__ A, const float* __restrict__ B,
           float* __restrict__ C,
           const float* __restrict__ P1, const float* __restrict__ P2,
           const float* __restrict__ P3,
           int Kdim, int lda, int ldb, int ldc,
           size_t aG, size_t aS, size_t bG, size_t bS, size_t cG, size_t cS,
           int mZ) {
    extern __shared__ char smem[];
    const uint32_t sb = smem_to_u32(smem);

    const int tid = threadIdx.x;
    const int wid = tid >> 5, lane = tid & 31;
    const int wm = wid & 1, wn = wid >> 1;
    const int tr = lane >> 2, tq = lane & 3;
    const int g8 = lane >> 3, rl = lane & 7;

    const int z = blockIdx.z;
    const int graph = z & (NGRAPH - 1);
    const int split = z >> 4;
    A += aG * graph + aS * split;
    B += bG * graph + bS * split;
    float* Cp;
    int n0c;
    if (MULTI) {
        float* bufs[3] = { C, (float*)P1, (float*)P2 };
        Cp = bufs[blockIdx.x >> 1];
        n0c = (blockIdx.x & 1) * BN;
    } else {
        Cp = C + cG * graph + cS * split;
        n0c = blockIdx.x * BN;
    }
    const int m0 = blockIdx.y * BM + mZ * graph;
    const int n0 = blockIdx.x * BN;      // operand-B offset

    // per-lane relative fragment byte offsets within slots
    uint32_t aRel, bRel;
    if (TA == 0) aRel = (uint32_t)(((wm * 64 + (g8 & 1) * 8 + rl) * 36 + (g8 >> 1) * 4) * 4);
    else         aRel = (uint32_t)((tq * 136 + wm * 64 + tr) * 4);
    if (TB == 0) bRel = (uint32_t)(((wn * 64 + (g8 >> 1) * 8 + rl) * 36 + (g8 & 1) * 4) * 4);
    else         bRel = (uint32_t)((tq * 264 + wn * 64 + tr) * 4);

    // cp.async issue for one pipeline stage
    auto issue = [&](int stage, int ktile) {
        const int k0 = ktile * BK;
        uint32_t slotA = sb + (uint32_t)stage * STAGE_BYTES;
        uint32_t slotB = slotA + A_SLOT_BYTES;
        if (TA == 0) {
            int row = tid >> 1, cb = (tid & 1) * 16;
            const float* s = A + (size_t)(m0 + row) * lda + k0 + cb;
            uint32_t d = slotA + (uint32_t)((row * 36 + cb) * 4);
#pragma unroll
            for (int j = 0; j < 4; ++j) cpa16(d + j * 16, s + j * 4);
        } else {
            int kr = tid >> 3, c = (tid & 7) * 4;
            const float* s = A + (size_t)(k0 + kr) * lda + m0 + c;
            uint32_t d = slotA + (uint32_t)((kr * 136 + c) * 4);
#pragma unroll
            for (int j = 0; j < 4; ++j) cpa16(d + j * 128, s + j * 32);
        }
        if (TB == 0) {
            int row = tid;                                 // 256 rows
            const float* s = B + (size_t)(n0 + row) * ldb + k0;
            uint32_t d = slotB + (uint32_t)(row * 36 * 4);
#pragma unroll
            for (int j = 0; j < 8; ++j) cpa16(d + j * 16, s + j * 4);
        } else {
            int kr = tid >> 3, c = (tid & 7) * 4;
            const float* s = B + (size_t)(k0 + kr) * ldb + n0 + c;
            uint32_t d = slotB + (uint32_t)((kr * 264 + c) * 4);
#pragma unroll
            for (int j = 0; j < 8; ++j) cpa16(d + j * 128, s + j * 32);
        }
    };

    float acc[4][8][4] = {};

    // prologue: stages 0, 1
    issue(0, 0); CP_COMMIT();
    issue(1, 1); CP_COMMIT();

    const int nK = Kdim / BK;
    for (int kt = 0; kt < nK; ++kt) {
        if (kt + 2 < nK) {
            issue((kt + 2) % NSTAGE, kt + 2); CP_COMMIT();
            asm volatile("cp.async.wait_group 2;" ::: "memory");
        } else if (kt + 1 < nK) {
            asm volatile("cp.async.wait_group 1;" ::: "memory");
        } else {
            asm volatile("cp.async.wait_group 0;" ::: "memory");
        }
        __syncthreads();

        uint32_t sA = sb + (uint32_t)(kt % NSTAGE) * STAGE_BYTES;
        uint32_t sB = sA + A_SLOT_BYTES;
#pragma unroll
        for (int kblk = 0; kblk < 4; ++kblk) {
            uint32_t afr[4][4];
            uint32_t bfr[8][2];
            if (TA == 0) {
#pragma unroll
                for (int mi = 0; mi < 4; ++mi)
                    ldsm_x4(afr[mi], sA + aRel + (uint32_t)(mi * 2304 + kblk * 32));
            } else {
#pragma unroll
                for (int mi = 0; mi < 4; ++mi) {
                    uint32_t base = sA + aRel + (uint32_t)(kblk * 4352 + mi * 64);
                    afr[mi][0] = lds32(base);
                    afr[mi][1] = lds32(base + 32);
                    afr[mi][2] = lds32(base + 2176);
                    afr[mi][3] = lds32(base + 2208);
                }
            }
            if (TB == 0) {
#pragma unroll
                for (int p = 0; p < 4; ++p) {
                    uint32_t t4[4];
                    ldsm_x4(t4, sB + bRel + (uint32_t)(p * 2304 + kblk * 32));
                    bfr[2 * p + 0][0] = t4[0]; bfr[2 * p + 0][1] = t4[1];
                    bfr[2 * p + 1][0] = t4[2]; bfr[2 * p + 1][1] = t4[3];
                }
            } else {
#pragma unroll
                for (int ni = 0; ni < 8; ++ni) {
                    uint32_t base = sB + bRel + (uint32_t)(kblk * 8448 + ni * 32);
                    bfr[ni][0] = lds32(base);
                    bfr[ni][1] = lds32(base + 4224);
                }
            }
#pragma unroll
            for (int mi = 0; mi < 4; ++mi)
#pragma unroll
                for (int ni = 0; ni < 8; ++ni)
                    mma_tf32(acc[mi][ni], afr[mi], bfr[ni]);
        }
        __syncthreads();
    }

    // ---------------- epilogue ----------------
#pragma unroll
    for (int mi = 0; mi < 4; ++mi) {
        int rbase = m0 + wm * 64 + mi * 16 + tr;
#pragma unroll
        for (int half = 0; half < 2; ++half) {
            size_t row = (size_t)rbase + half * 8;
            float dinv = 0.0f;
            if (EPI == EPI_ATT) dinv = 1.0f / P3[row];
#pragma unroll
            for (int ni = 0; ni < 8; ++ni) {
                int col = n0c + wn * 64 + ni * 8 + tq * 2;
                float c0 = acc[mi][ni][half * 2 + 0];
                float c1 = acc[mi][ni][half * 2 + 1];
                float* dst = Cp + row * (size_t)ldc + col;
                float2 o;
                if (EPI == EPI_NONE) {
                    o.x = c0; o.y = c1;
                } else if (EPI == EPI_BIAS) {
                    float2 bv = *(const float2*)(P1 + col);
                    o.x = c0 + bv.x; o.y = c1 + bv.y;
                } else {
                    float2 vv = *(const float2*)(P1 + row * HID + col);
                    float2 hh = *(const float2*)(P2 + row * HID + col);
                    o.x = ((c0 + 4096.0f * vv.x) * dinv + hh.x) * 0.5f;
                    o.y = ((c1 + 4096.0f * vv.y) * dinv + hh.y) * 0.5f;
                }
                if (RND) { o.x = roundtf(o.x); o.y = roundtf(o.y); }
                *(float2*)dst = o;
            }
        }
    }
}

// ================= elementwise kernels =================
__device__ __forceinline__ float wred(float v) {
#pragma unroll
    for (int o = 16; o; o >>= 1) v += __shfl_xor_sync(0xffffffffu, v, o);
    return v;
}

__global__ void round_copy(const float4* __restrict__ in, float4* __restrict__ out, int n4) {
    int i = blockIdx.x * blockDim.x + threadIdx.x;
    if (i < n4) {
        float4 v = in[i];
        v.x = roundtf(v.x); v.y = roundtf(v.y);
        v.z = roundtf(v.z); v.w = roundtf(v.w);
        out[i] = v;
    }
}

__global__ void ln_relu(const float* __restrict__ in, float* __restrict__ out,
                        const float* __restrict__ g, const float* __restrict__ b, int rnd) {
    size_t warp = ((size_t)blockIdx.x * blockDim.x + threadIdx.x) >> 5;
    int lane = threadIdx.x & 31;
    const float4* src = (const float4*)(in + warp * HID);
    float4 v[4];
    float s = 0.0f, s2 = 0.0f;
#pragma unroll
    for (int c = 0; c < 4; ++c) {
        v[c] = src[lane + 32 * c];
        s  += v[c].x + v[c].y + v[c].z + v[c].w;
        s2 += v[c].x * v[c].x + v[c].y * v[c].y + v[c].z * v[c].z + v[c].w * v[c].w;
    }
    s = wred(s); s2 = wred(s2);
    float mu = s * (1.0f / HID);
    float var = s2 * (1.0f / HID) - mu * mu;
    float rstd = rsqrtf(var + LN_EPS);
    float4* dst = (float4*)(out + warp * HID);
#pragma unroll
    for (int c = 0; c < 4; ++c) {
        int i4 = lane + 32 * c;
        float4 gg = ((const float4*)g)[i4];
        float4 bb = ((const float4*)b)[i4];
        float4 o;
        o.x = fmaxf(0.0f, (v[c].x - mu) * rstd * gg.x + bb.x);
        o.y = fmaxf(0.0f, (v[c].y - mu) * rstd * gg.y + bb.y);
        o.z = fmaxf(0.0f, (v[c].z - mu) * rstd * gg.z + bb.z);
        o.w = fmaxf(0.0f, (v[c].w - mu) * rstd * gg.w + bb.w);
        if (rnd) {
            o.x = roundtf(o.x); o.y = roundtf(o.y);
            o.z = roundtf(o.z); o.w = roundtf(o.w);
        }
        dst[i4] = o;
    }
}

__global__ void norm_qk(float* __restrict__ X) {
    size_t warp = ((size_t)blockIdx.x * blockDim.x + threadIdx.x) >> 5;
    int lane = threadIdx.x & 31;
    float4* p = (float4*)(X + warp * HID);
    float4 v[4];
    float s2 = 0.0f;
#pragma unroll
    for (int c = 0; c < 4; ++c) {
        v[c] = p[lane + 32 * c];
        if (v[c].x == 0.0f) v[c].x = QK_EPS;
        if (v[c].y == 0.0f) v[c].y = QK_EPS;
        if (v[c].z == 0.0f) v[c].z = QK_EPS;
        if (v[c].w == 0.0f) v[c].w = QK_EPS;
        s2 += v[c].x * v[c].x + v[c].y * v[c].y + v[c].z * v[c].z + v[c].w * v[c].w;
    }
    s2 = wred(s2);
    float rn = rsqrtf(s2);
#pragma unroll
    for (int c = 0; c < 4; ++c) {
        v[c].x = roundtf(v[c].x * rn); v[c].y = roundtf(v[c].y * rn);
        v[c].z = roundtf(v[c].z * rn); v[c].w = roundtf(v[c].w * rn);
        p[lane + 32 * c] = v[c];
    }
}

__global__ void kvs_reduce(const float* __restrict__ Part, float* __restrict__ KVS) {
    size_t o = (size_t)blockIdx.x * blockDim.x + threadIdx.x;
    size_t graph = o >> 18;
    size_t r = o & ((1u << 18) - 1);
    float s = 0.0f;
#pragma unroll
    for (int sp = 0; sp < SK; ++sp)
        s += Part[((size_t)sp * NGRAPH + graph) * HID * HID + r];
    KVS[o] = roundtf(s);
}

__global__ void ksum_part(const float* __restrict__ Kmat, float* __restrict__ Part) {
    int graph = blockIdx.x >> 3, chunk = blockIdx.x & 7;
    int ch = threadIdx.x;
    size_t base = ((size_t)graph * NNODES + (size_t)chunk * (NNODES / SPLITS)) * HID + ch;
    float s = 0.0f;
#pragma unroll 8
    for (int r = 0; r < NNODES / SPLITS; ++r)
        s += Kmat[base + (size_t)r * HID];
    Part[(size_t)blockIdx.x * HID + ch] = s;
}

__global__ void ksum_reduce(const float* __restrict__ Part, float* __restrict__ KS) {
    int idx = blockIdx.x * blockDim.x + threadIdx.x;
    int graph = idx >> 9, ch = idx & 511;
    float s = 0.0f;
#pragma unroll
    for (int c = 0; c < SPLITS; ++c)
        s += Part[((size_t)(graph * SPLITS + c)) * HID + ch];
    KS[idx] = s;
}

__global__ void denom_kernel(const float* __restrict__ Q, const float* __restrict__ KS,
                             float* __restrict__ den) {
    size_t warp = ((size_t)blockIdx.x * blockDim.x + threadIdx.x) >> 5;
    int lane = threadIdx.x & 31;
    int graph = (int)(warp >> 12);
    const float4* qp = (const float4*)(Q + warp * HID);
    const float4* kp = (const float4*)(KS + (size_t)graph * HID);
    float s = 0.0f;
#pragma unroll
    for (int c = 0; c < 4; ++c) {
        float4 a = qp[lane + 32 * c];
        float4 b = kp[lane + 32 * c];
        s += a.x * b.x + a.y * b.y + a.z * b.z + a.w * b.w;
    }
    s = wred(s);
    if (lane == 0) den[warp] = s + (float)NNODES;
}

// ================= launch =================
extern "C" void kernel_launch(void* const* d_in, const int* in_sizes, int n_in,
                              void* d_out, int out_size) {
    const float* x     = (const float*)d_in[0];
    const float* fc0_w = (const float*)d_in[1];
    const float* fc0_b = (const float*)d_in[2];
    const float* ln_g[3] = { (const float*)d_in[3], (const float*)d_in[8],  (const float*)d_in[13] };
    const float* ln_b[3] = { (const float*)d_in[4], (const float*)d_in[9],  (const float*)d_in[14] };
    const float* qw[2] = { (const float*)d_in[5],  (const float*)d_in[10] };
    const float* kw[2] = { (const float*)d_in[6],  (const float*)d_in[11] };
    const float* vw[2] = { (const float*)d_in[7],  (const float*)d_in[12] };
    float* out = (float*)d_out;
    // batch = repeat(arange(16), 4096): argsort and rev_perm are identities.

    float *h, *q, *k, *v, *t, *xr, *wr, *kvp, *kvs, *ksp, *ks, *den;
    cudaGetSymbolAddress((void**)&h,   g_h);
    cudaGetSymbolAddress((void**)&q,   g_q);
    cudaGetSymbolAddress((void**)&k,   g_k);
    cudaGetSymbolAddress((void**)&v,   g_v);
    cudaGetSymbolAddress((void**)&t,   g_t);
    cudaGetSymbolAddress((void**)&xr,  g_xr);
    cudaGetSymbolAddress((void**)&wr,  g_wr);
    cudaGetSymbolAddress((void**)&kvp, g_kvp);
    cudaGetSymbolAddress((void**)&kvs, g_kvs);
    cudaGetSymbolAddress((void**)&ksp, g_ksp);
    cudaGetSymbolAddress((void**)&ks,  g_ks);
    cudaGetSymbolAddress((void**)&den, g_den);

    cudaFuncSetAttribute((const void*)mm_tc<0,0,EPI_BIAS,0,0>,
                         cudaFuncAttributeMaxDynamicSharedMemorySize, SMEM_BYTES);
    cudaFuncSetAttribute((const void*)mm_tc<0,0,EPI_NONE,1,1>,
                         cudaFuncAttributeMaxDynamicSharedMemorySize, SMEM_BYTES);
    cudaFuncSetAttribute((const void*)mm_tc<1,1,EPI_NONE,0,0>,
                         cudaFuncAttributeMaxDynamicSharedMemorySize, SMEM_BYTES);
    cudaFuncSetAttribute((const void*)mm_tc<0,1,EPI_ATT,0,0>,
                         cudaFuncAttributeMaxDynamicSharedMemorySize, SMEM_BYTES);

    // rounded weights: fc0 then per-layer [3*HID, HID] contiguous (q,k,v)
    float* wr_fc0 = wr;
    float* wr_l[2] = { wr + (size_t)HID * INCH,
                       wr + (size_t)HID * INCH + 3 * (size_t)HID * HID };

    round_copy<<<(TOTAL * INCH / 4 + 255) / 256, 256>>>((const float4*)x, (float4*)xr, TOTAL * INCH / 4);
    round_copy<<<(HID * INCH / 4 + 255) / 256, 256>>>((const float4*)fc0_w, (float4*)wr_fc0, HID * INCH / 4);
    const float* wsrc[2][3] = { { qw[0], kw[0], vw[0] }, { qw[1], kw[1], vw[1] } };
    for (int l = 0; l < 2; ++l)
        for (int j = 0; j < 3; ++j)
            round_copy<<<(HID * HID / 4 + 255) / 256, 256>>>(
                (const float4*)wsrc[l][j], (float4*)(wr_l[l] + (size_t)j * HID * HID), HID * HID / 4);

    const int row_blocks = TOTAL / 8;

    // h = relu(LN(x @ fc0_w^T + b))   [h rounded to tf32]
    mm_tc<0,0,EPI_BIAS,0,0><<<dim3(HID / BN, TOTAL / BM), 256, SMEM_BYTES>>>(
        xr, wr_fc0, t, fc0_b, nullptr, nullptr, INCH, INCH, INCH, HID,
        0, 0, 0, 0, 0, 0, 0);
    ln_relu<<<row_blocks, 256>>>(t, h, ln_g[0], ln_b[0], 1);

    for (int l = 0; l < 2; ++l) {
        float* dst = (l == 1) ? out : h;
        // merged QKV: B = [1536, 512] rounded weights; outputs routed to q/k/v
        mm_tc<0,0,EPI_NONE,1,1><<<dim3(3 * HID / BN, TOTAL / BM), 256, SMEM_BYTES>>>(
            h, wr_l[l], q, k, v, nullptr, HID, HID, HID, HID,
            0, 0, 0, 0, 0, 0, 0);
        norm_qk<<<row_blocks, 256>>>(q);
        norm_qk<<<row_blocks, 256>>>(k);
        // kvp[split][g][m,d] = sum_{n in split} k[g,n,m] * v[g,n,d]
        mm_tc<1,1,EPI_NONE,0,0><<<dim3(HID / BN, HID / BM, NGRAPH * SK), 256, SMEM_BYTES>>>(
            k, v, kvp, nullptr, nullptr, nullptr, NNODES / SK, HID, HID, HID,
            (size_t)NNODES * HID, (size_t)(NNODES / SK) * HID,
            (size_t)NNODES * HID, (size_t)(NNODES / SK) * HID,
            (size_t)HID * HID, (size_t)NGRAPH * HID * HID, 0);
        kvs_reduce<<<(NGRAPH * HID * HID) / 256, 256>>>(kvp, kvs);
        ksum_part<<<NGRAPH * SPLITS, HID>>>(k, ksp);
        ksum_reduce<<<(NGRAPH * HID) / 256, 256>>>(ksp, ks);
        denom_kernel<<<row_blocks, 256>>>(q, ks, den);
        // t = ((q @ kvs + N*v)/den + h)/2
        mm_tc<0,1,EPI_ATT,0,0><<<dim3(HID / BN, NNODES / BM, NGRAPH), 256, SMEM_BYTES>>>(
            q, kvs, t, v, h, den, HID, HID, HID, HID,
            0, 0, (size_t)HID * HID, 0, 0, 0, NNODES);
        ln_relu<<<row_blocks, 256>>>(t, dst, ln_g[l + 1], ln_b[l + 1], (l == 0) ? 1 : 0);
    }
}

// round 6
// speedup vs baseline: 1.0858x; 1.0858x over previous
#include <cuda_runtime.h>
#include <cstdint>
#include <cstddef>

// ---------------- problem constants ----------------
#define TOTAL    65536          // B_GRAPHS * N_NODES
#define NGRAPH   16
#define NNODES   4096
#define INCH     256
#define HID      512
#define LN_EPS   1e-5f
#define QK_EPS   1e-6f
#define SK       4              // split-K for kv GEMM
#define KBLOCKS  (TOTAL / 8)    // 8192 k-partial blocks (8 rows each)

// ---------------- GEMM tiling (R4-proven: 128x128, 2 CTAs/SM) ----------------
#define BM 128
#define BN 128
#define BK 32
#define A_SLOT_BYTES 18432              // max(128*36*4, 32*136*4)
#define STAGE_BYTES (2 * A_SLOT_BYTES)  // A slot + B slot
#define NSTAGE 3
#define SMEM_BYTES (NSTAGE * STAGE_BYTES)   // 110592

// epilogue modes
#define EPI_NONE 0
#define EPI_BIAS 1
#define EPI_ATT  2

// ---------------- scratch (device globals; no allocation) ----------------
__device__ float g_h  [(size_t)TOTAL * HID];
__device__ float g_q  [(size_t)TOTAL * HID];
__device__ float g_k  [(size_t)TOTAL * HID];
__device__ float g_v  [(size_t)TOTAL * HID];
__device__ float g_t  [(size_t)TOTAL * HID];
__device__ float g_xr [(size_t)TOTAL * INCH];
__device__ float g_wr [(size_t)(HID * INCH + 6 * HID * HID)];
__device__ float g_kvp [(size_t)SK * NGRAPH * HID * HID];
__device__ float g_kvs [(size_t)NGRAPH * HID * HID];
__device__ float g_ksp [(size_t)KBLOCKS * HID];
__device__ float g_ks  [(size_t)NGRAPH * HID];
__device__ float g_den [(size_t)TOTAL];

// ---------------- helpers ----------------
__device__ __forceinline__ uint32_t smem_to_u32(const void* p) {
    uint32_t a;
    asm("{ .reg .u64 t; cvta.to.shared.u64 t, %1; cvt.u32.u64 %0, t; }" : "=r"(a) : "l"(p));
    return a;
}
__device__ __forceinline__ uint32_t f2tf32(float f) {
    uint32_t u;
    asm("cvt.rna.tf32.f32 %0, %1;" : "=r"(u) : "f"(f));
    return u;
}
__device__ __forceinline__ float roundtf(float f) { return __uint_as_float(f2tf32(f)); }

__device__ __forceinline__ void mma_tf32(float (&c)[4], const uint32_t (&a)[4],
                                         const uint32_t (&b)[2]) {
    asm volatile(
        "mma.sync.aligned.m16n8k8.row.col.f32.tf32.tf32.f32 "
        "{%0,%1,%2,%3}, {%4,%5,%6,%7}, {%8,%9}, {%0,%1,%2,%3};"
        : "+f"(c[0]), "+f"(c[1]), "+f"(c[2]), "+f"(c[3])
        : "r"(a[0]), "r"(a[1]), "r"(a[2]), "r"(a[3]), "r"(b[0]), "r"(b[1]));
}
__device__ __forceinline__ void ldsm_x4(uint32_t (&r)[4], uint32_t addr) {
    asm volatile("ldmatrix.sync.aligned.m8n8.x4.shared.b16 {%0,%1,%2,%3}, [%4];"
        : "=r"(r[0]), "=r"(r[1]), "=r"(r[2]), "=r"(r[3]) : "r"(addr));
}
__device__ __forceinline__ uint32_t lds32(uint32_t addr) {
    uint32_t v;
    asm volatile("ld.shared.b32 %0, [%1];" : "=r"(v) : "r"(addr));
    return v;
}
__device__ __forceinline__ void cpa16(uint32_t dst, const float* src) {
    asm volatile("cp.async.cg.shared.global [%0], [%1], 16;" :: "r"(dst), "l"(src) : "memory");
}
#define CP_COMMIT() asm volatile("cp.async.commit_group;" ::: "memory")

// ================= tf32 mma.sync GEMM, 128x128 tile, 3-stage cp.async =================
// C[m0+i, n0+j] (+epilogue) = sum_k A(i,k) * B(j,k)
// TR==0: operand K-contiguous (slot S[row][k], stride 36, ldmatrix frags)
// TR==1: operand MN-contiguous (slot S[k][col], stride 136, LDS.32 frags)
// MULTI: merged QKV — B is [1536,512]; output buffer = blockIdx.x>>2 (C/P1/P2).
template <int TA, int TB, int EPI, int RND, int MULTI>
__global__ __launch_bounds__(256, 2)
void mm_tc(const float* __restrict__ A, const float* __restrict__ B,
           float* __restrict__ C,
           const float* __restrict__ P1, const float* __restrict__ P2,
           const float* __restrict__ P3,
           int Kdim, int lda, int ldb, int ldc,
           size_t aG, size_t aS, size_t bG, size_t bS, size_t cG, size_t cS,
           int mZ) {
    extern __shared__ char smem[];
    const uint32_t sb = smem_to_u32(smem);

    const int tid = threadIdx.x;
    const int wid = tid >> 5, lane = tid & 31;
    const int wm = wid & 1, wn = wid >> 1;
    const int tr = lane >> 2, tq = lane & 3;
    const int g8 = lane >> 3, rl = lane & 7;

    const int z = blockIdx.z;
    const int graph = z & (NGRAPH - 1);
    const int split = z >> 4;
    A += aG * graph + aS * split;
    B += bG * graph + bS * split;
    float* Cp;
    int n0c;
    if (MULTI) {
        float* bufs[3] = { C, (float*)P1, (float*)P2 };
        Cp = bufs[blockIdx.x >> 2];
        n0c = (blockIdx.x & 3) * BN;
    } else {
        Cp = C + cG * graph + cS * split;
        n0c = blockIdx.x * BN;
    }
    const int m0 = blockIdx.y * BM + mZ * graph;
    const int n0 = blockIdx.x * BN;      // operand-B row offset

    // per-lane relative fragment byte offsets within slots
    uint32_t aRel, bRel;
    if (TA == 0) aRel = (uint32_t)(((wm * 64 + (g8 & 1) * 8 + rl) * 36 + (g8 >> 1) * 4) * 4);
    else         aRel = (uint32_t)((tq * 136 + wm * 64 + tr) * 4);
    if (TB == 0) bRel = (uint32_t)(((wn * 32 + (g8 >> 1) * 8 + rl) * 36 + (g8 & 1) * 4) * 4);
    else         bRel = (uint32_t)((tq * 136 + wn * 32 + tr) * 4);

    // cp.async issue for one pipeline stage
    auto issue = [&](int stage, int ktile) {
        const int k0 = ktile * BK;
        uint32_t slotA = sb + (uint32_t)stage * STAGE_BYTES;
        uint32_t slotB = slotA + A_SLOT_BYTES;
        if (TA == 0) {
            int row = tid >> 1, cb = (tid & 1) * 16;
            const float* s = A + (size_t)(m0 + row) * lda + k0 + cb;
            uint32_t d = slotA + (uint32_t)((row * 36 + cb) * 4);
#pragma unroll
            for (int j = 0; j < 4; ++j) cpa16(d + j * 16, s + j * 4);
        } else {
            int kr = tid >> 3, c = (tid & 7) * 4;
            const float* s = A + (size_t)(k0 + kr) * lda + m0 + c;
            uint32_t d = slotA + (uint32_t)((kr * 136 + c) * 4);
#pragma unroll
            for (int j = 0; j < 4; ++j) cpa16(d + j * 128, s + j * 32);
        }
        if (TB == 0) {
            int row = tid >> 1, cb = (tid & 1) * 16;
            const float* s = B + (size_t)(n0 + row) * ldb + k0 + cb;
            uint32_t d = slotB + (uint32_t)((row * 36 + cb) * 4);
#pragma unroll
            for (int j = 0; j < 4; ++j) cpa16(d + j * 16, s + j * 4);
        } else {
            int kr = tid >> 3, c = (tid & 7) * 4;
            const float* s = B + (size_t)(k0 + kr) * ldb + n0 + c;
            uint32_t d = slotB + (uint32_t)((kr * 136 + c) * 4);
#pragma unroll
            for (int j = 0; j < 4; ++j) cpa16(d + j * 128, s + j * 32);
        }
    };

    float acc[4][4][4] = {};

    // prologue: stages 0, 1
    issue(0, 0); CP_COMMIT();
    issue(1, 1); CP_COMMIT();

    const int nK = Kdim / BK;
    for (int kt = 0; kt < nK; ++kt) {
        if (kt + 2 < nK) {
            issue((kt + 2) % NSTAGE, kt + 2); CP_COMMIT();
            asm volatile("cp.async.wait_group 2;" ::: "memory");
        } else if (kt + 1 < nK) {
            asm volatile("cp.async.wait_group 1;" ::: "memory");
        } else {
            asm volatile("cp.async.wait_group 0;" ::: "memory");
        }
        __syncthreads();

        uint32_t sA = sb + (uint32_t)(kt % NSTAGE) * STAGE_BYTES;
        uint32_t sB = sA + A_SLOT_BYTES;
#pragma unroll
        for (int kblk = 0; kblk < 4; ++kblk) {
            uint32_t afr[4][4];
            uint32_t bfr[4][2];
            if (TA == 0) {
#pragma unroll
                for (int mi = 0; mi < 4; ++mi)
                    ldsm_x4(afr[mi], sA + aRel + (uint32_t)(mi * 2304 + kblk * 32));
            } else {
#pragma unroll
                for (int mi = 0; mi < 4; ++mi) {
                    uint32_t base = sA + aRel + (uint32_t)(kblk * 4352 + mi * 64);
                    afr[mi][0] = lds32(base);
                    afr[mi][1] = lds32(base + 32);
                    afr[mi][2] = lds32(base + 2176);
                    afr[mi][3] = lds32(base + 2208);
                }
            }
            if (TB == 0) {
#pragma unroll
                for (int p = 0; p < 2; ++p) {
                    uint32_t t4[4];
                    ldsm_x4(t4, sB + bRel + (uint32_t)(p * 2304 + kblk * 32));
                    bfr[2 * p + 0][0] = t4[0]; bfr[2 * p + 0][1] = t4[1];
                    bfr[2 * p + 1][0] = t4[2]; bfr[2 * p + 1][1] = t4[3];
                }
            } else {
#pragma unroll
                for (int ni = 0; ni < 4; ++ni) {
                    uint32_t base = sB + bRel + (uint32_t)(kblk * 4352 + ni * 32);
                    bfr[ni][0] = lds32(base);
                    bfr[ni][1] = lds32(base + 2176);
                }
            }
#pragma unroll
            for (int mi = 0; mi < 4; ++mi)
#pragma unroll
                for (int ni = 0; ni < 4; ++ni)
                    mma_tf32(acc[mi][ni], afr[mi], bfr[ni]);
        }
        __syncthreads();
    }

    // ---------------- epilogue ----------------
#pragma unroll
    for (int mi = 0; mi < 4; ++mi) {
        int rbase = m0 + wm * 64 + mi * 16 + tr;
#pragma unroll
        for (int half = 0; half < 2; ++half) {
            size_t row = (size_t)rbase + half * 8;
            float dinv = 0.0f;
            if (EPI == EPI_ATT) dinv = 1.0f / P3[row];
#pragma unroll
            for (int ni = 0; ni < 4; ++ni) {
                int col = n0c + wn * 32 + ni * 8 + tq * 2;
                float c0 = acc[mi][ni][half * 2 + 0];
                float c1 = acc[mi][ni][half * 2 + 1];
                float* dst = Cp + row * (size_t)ldc + col;
                float2 o;
                if (EPI == EPI_NONE) {
                    o.x = c0; o.y = c1;
                } else if (EPI == EPI_BIAS) {
                    float2 bv = *(const float2*)(P1 + col);
                    o.x = c0 + bv.x; o.y = c1 + bv.y;
                } else {
                    float2 vv = *(const float2*)(P1 + row * HID + col);
                    float2 hh = *(const float2*)(P2 + row * HID + col);
                    o.x = ((c0 + 4096.0f * vv.x) * dinv + hh.x) * 0.5f;
                    o.y = ((c1 + 4096.0f * vv.y) * dinv + hh.y) * 0.5f;
                }
                if (RND) { o.x = roundtf(o.x); o.y = roundtf(o.y); }
                *(float2*)dst = o;
            }
        }
    }
}

// ================= elementwise kernels =================
__device__ __forceinline__ float wred(float v) {
#pragma unroll
    for (int o = 16; o; o >>= 1) v += __shfl_xor_sync(0xffffffffu, v, o);
    return v;
}

__global__ void round_copy(const float4* __restrict__ in, float4* __restrict__ out, int n4) {
    int i = blockIdx.x * blockDim.x + threadIdx.x;
    if (i < n4) {
        float4 v = in[i];
        v.x = roundtf(v.x); v.y = roundtf(v.y);
        v.z = roundtf(v.z); v.w = roundtf(v.w);
        out[i] = v;
    }
}

__global__ void ln_relu(const float* __restrict__ in, float* __restrict__ out,
                        const float* __restrict__ g, const float* __restrict__ b, int rnd) {
    size_t warp = ((size_t)blockIdx.x * blockDim.x + threadIdx.x) >> 5;
    int lane = threadIdx.x & 31;
    const float4* src = (const float4*)(in + warp * HID);
    float4 v[4];
    float s = 0.0f, s2 = 0.0f;
#pragma unroll
    for (int c = 0; c < 4; ++c) {
        v[c] = src[lane + 32 * c];
        s  += v[c].x + v[c].y + v[c].z + v[c].w;
        s2 += v[c].x * v[c].x + v[c].y * v[c].y + v[c].z * v[c].z + v[c].w * v[c].w;
    }
    s = wred(s); s2 = wred(s2);
    float mu = s * (1.0f / HID);
    float var = s2 * (1.0f / HID) - mu * mu;
    float rstd = rsqrtf(var + LN_EPS);
    float4* dst = (float4*)(out + warp * HID);
#pragma unroll
    for (int c = 0; c < 4; ++c) {
        int i4 = lane + 32 * c;
        float4 gg = ((const float4*)g)[i4];
        float4 bb = ((const float4*)b)[i4];
        float4 o;
        o.x = fmaxf(0.0f, (v[c].x - mu) * rstd * gg.x + bb.x);
        o.y = fmaxf(0.0f, (v[c].y - mu) * rstd * gg.y + bb.y);
        o.z = fmaxf(0.0f, (v[c].z - mu) * rstd * gg.z + bb.z);
        o.w = fmaxf(0.0f, (v[c].w - mu) * rstd * gg.w + bb.w);
        if (rnd) {
            o.x = roundtf(o.x); o.y = roundtf(o.y);
            o.z = roundtf(o.z); o.w = roundtf(o.w);
        }
        dst[i4] = o;
    }
}

// k: eps-substitute, L2-normalize, round, store; ALSO write 8-row column partials.
// 256 threads = 8 warps = 8 rows per block.
__global__ void norm_k(float* __restrict__ X, float* __restrict__ Part) {
    __shared__ float sacc[8][HID];     // 16 KB
    int w = threadIdx.x >> 5, lane = threadIdx.x & 31;
    size_t warp = (size_t)blockIdx.x * 8 + w;
    float4* p = (float4*)(X + warp * HID);
    float4 v[4];
    float s2 = 0.0f;
#pragma unroll
    for (int c = 0; c < 4; ++c) {
        v[c] = p[lane + 32 * c];
        if (v[c].x == 0.0f) v[c].x = QK_EPS;
        if (v[c].y == 0.0f) v[c].y = QK_EPS;
        if (v[c].z == 0.0f) v[c].z = QK_EPS;
        if (v[c].w == 0.0f) v[c].w = QK_EPS;
        s2 += v[c].x * v[c].x + v[c].y * v[c].y + v[c].z * v[c].z + v[c].w * v[c].w;
    }
    s2 = wred(s2);
    float rn = rsqrtf(s2);
#pragma unroll
    for (int c = 0; c < 4; ++c) {
        v[c].x = roundtf(v[c].x * rn); v[c].y = roundtf(v[c].y * rn);
        v[c].z = roundtf(v[c].z * rn); v[c].w = roundtf(v[c].w * rn);
        p[lane + 32 * c] = v[c];
        *(float4*)&sacc[w][(lane + 32 * c) * 4] = v[c];
    }
    __syncthreads();
#pragma unroll
    for (int ch = threadIdx.x; ch < HID; ch += 256) {
        float s = 0.0f;
#pragma unroll
        for (int r = 0; r < 8; ++r) s += sacc[r][ch];
        Part[(size_t)blockIdx.x * HID + ch] = s;
    }
}

// KS[g][ch] = sum over 512 blocks of that graph's partials
__global__ void ksum_reduce(const float* __restrict__ Part, float* __restrict__ KS) {
    int idx = blockIdx.x * blockDim.x + threadIdx.x;    // 16*512
    int graph = idx >> 9, ch = idx & 511;
    float s = 0.0f;
    const float* p = Part + ((size_t)graph * 512) * HID + ch;
#pragma unroll 8
    for (int b = 0; b < 512; ++b) s += p[(size_t)b * HID];
    KS[idx] = s;
}

// q: eps-substitute, normalize, round, store; ALSO den[row] = dot(qn, ks[graph]) + N
__global__ void norm_q_den(float* __restrict__ X, const float* __restrict__ KS,
                           float* __restrict__ den) {
    size_t warp = ((size_t)blockIdx.x * blockDim.x + threadIdx.x) >> 5;
    int lane = threadIdx.x & 31;
    int graph = (int)(warp >> 12);
    float4* p = (float4*)(X + warp * HID);
    const float4* kp = (const float4*)(KS + (size_t)graph * HID);
    float4 v[4];
    float s2 = 0.0f;
#pragma unroll
    for (int c = 0; c < 4; ++c) {
        v[c] = p[lane + 32 * c];
        if (v[c].x == 0.0f) v[c].x = QK_EPS;
        if (v[c].y == 0.0f) v[c].y = QK_EPS;
        if (v[c].z == 0.0f) v[c].z = QK_EPS;
        if (v[c].w == 0.0f) v[c].w = QK_EPS;
        s2 += v[c].x * v[c].x + v[c].y * v[c].y + v[c].z * v[c].z + v[c].w * v[c].w;
    }
    s2 = wred(s2);
    float rn = rsqrtf(s2);
    float d = 0.0f;
#pragma unroll
    for (int c = 0; c < 4; ++c) {
        v[c].x = roundtf(v[c].x * rn); v[c].y = roundtf(v[c].y * rn);
        v[c].z = roundtf(v[c].z * rn); v[c].w = roundtf(v[c].w * rn);
        p[lane + 32 * c] = v[c];
        float4 kk = kp[lane + 32 * c];
        d += v[c].x * kk.x + v[c].y * kk.y + v[c].z * kk.z + v[c].w * kk.w;
    }
    d = wred(d);
    if (lane == 0) den[warp] = d + (float)NNODES;
}

__global__ void kvs_reduce(const float* __restrict__ Part, float* __restrict__ KVS) {
    size_t o = (size_t)blockIdx.x * blockDim.x + threadIdx.x;
    size_t graph = o >> 18;
    size_t r = o & ((1u << 18) - 1);
    float s = 0.0f;
#pragma unroll
    for (int sp = 0; sp < SK; ++sp)
        s += Part[((size_t)sp * NGRAPH + graph) * HID * HID + r];
    KVS[o] = roundtf(s);
}

// ================= launch =================
extern "C" void kernel_launch(void* const* d_in, const int* in_sizes, int n_in,
                              void* d_out, int out_size) {
    const float* x     = (const float*)d_in[0];
    const float* fc0_w = (const float*)d_in[1];
    const float* fc0_b = (const float*)d_in[2];
    const float* ln_g[3] = { (const float*)d_in[3], (const float*)d_in[8],  (const float*)d_in[13] };
    const float* ln_b[3] = { (const float*)d_in[4], (const float*)d_in[9],  (const float*)d_in[14] };
    const float* qw[2] = { (const float*)d_in[5],  (const float*)d_in[10] };
    const float* kw[2] = { (const float*)d_in[6],  (const float*)d_in[11] };
    const float* vw[2] = { (const float*)d_in[7],  (const float*)d_in[12] };
    float* out = (float*)d_out;
    // batch = repeat(arange(16), 4096): argsort and rev_perm are identities.

    float *h, *q, *k, *v, *t, *xr, *wr, *kvp, *kvs, *ksp, *ks, *den;
    cudaGetSymbolAddress((void**)&h,   g_h);
    cudaGetSymbolAddress((void**)&q,   g_q);
    cudaGetSymbolAddress((void**)&k,   g_k);
    cudaGetSymbolAddress((void**)&v,   g_v);
    cudaGetSymbolAddress((void**)&t,   g_t);
    cudaGetSymbolAddress((void**)&xr,  g_xr);
    cudaGetSymbolAddress((void**)&wr,  g_wr);
    cudaGetSymbolAddress((void**)&kvp, g_kvp);
    cudaGetSymbolAddress((void**)&kvs, g_kvs);
    cudaGetSymbolAddress((void**)&ksp, g_ksp);
    cudaGetSymbolAddress((void**)&ks,  g_ks);
    cudaGetSymbolAddress((void**)&den, g_den);

    cudaFuncSetAttribute((const void*)mm_tc<0,0,EPI_BIAS,0,0>,
                         cudaFuncAttributeMaxDynamicSharedMemorySize, SMEM_BYTES);
    cudaFuncSetAttribute((const void*)mm_tc<0,0,EPI_NONE,1,1>,
                         cudaFuncAttributeMaxDynamicSharedMemorySize, SMEM_BYTES);
    cudaFuncSetAttribute((const void*)mm_tc<1,1,EPI_NONE,0,0>,
                         cudaFuncAttributeMaxDynamicSharedMemorySize, SMEM_BYTES);
    cudaFuncSetAttribute((const void*)mm_tc<0,1,EPI_ATT,0,0>,
                         cudaFuncAttributeMaxDynamicSharedMemorySize, SMEM_BYTES);

    // rounded weights: fc0 then per-layer [3*HID, HID] contiguous (q,k,v)
    float* wr_fc0 = wr;
    float* wr_l[2] = { wr + (size_t)HID * INCH,
                       wr + (size_t)HID * INCH + 3 * (size_t)HID * HID };

    round_copy<<<(TOTAL * INCH / 4 + 255) / 256, 256>>>((const float4*)x, (float4*)xr, TOTAL * INCH / 4);
    round_copy<<<(HID * INCH / 4 + 255) / 256, 256>>>((const float4*)fc0_w, (float4*)wr_fc0, HID * INCH / 4);
    const float* wsrc[2][3] = { { qw[0], kw[0], vw[0] }, { qw[1], kw[1], vw[1] } };
    for (int l = 0; l < 2; ++l)
        for (int j = 0; j < 3; ++j)
            round_copy<<<(HID * HID / 4 + 255) / 256, 256>>>(
                (const float4*)wsrc[l][j], (float4*)(wr_l[l] + (size_t)j * HID * HID), HID * HID / 4);

    const int row_blocks = TOTAL / 8;

    // h = relu(LN(x @ fc0_w^T + b))   [h rounded to tf32]
    mm_tc<0,0,EPI_BIAS,0,0><<<dim3(HID / BN, TOTAL / BM), 256, SMEM_BYTES>>>(
        xr, wr_fc0, t, fc0_b, nullptr, nullptr, INCH, INCH, INCH, HID,
        0, 0, 0, 0, 0, 0, 0);
    ln_relu<<<row_blocks, 256>>>(t, h, ln_g[0], ln_b[0], 1);

    for (int l = 0; l < 2; ++l) {
        float* dst = (l == 1) ? out : h;
        // merged QKV: B = [1536, 512] rounded weights; outputs routed to q/k/v
        mm_tc<0,0,EPI_NONE,1,1><<<dim3(12, TOTAL / BM), 256, SMEM_BYTES>>>(
            h, wr_l[l], q, k, v, nullptr, HID, HID, HID, HID,
            0, 0, 0, 0, 0, 0, 0);
        norm_k<<<KBLOCKS, 256>>>(k, ksp);
        ksum_reduce<<<(NGRAPH * HID) / 256, 256>>>(ksp, ks);
        norm_q_den<<<row_blocks, 256>>>(q, ks, den);
        // kvp[split][g][m,d] = sum_{n in split} k[g,n,m] * v[g,n,d]
        mm_tc<1,1,EPI_NONE,0,0><<<dim3(HID / BN, HID / BM, NGRAPH * SK), 256, SMEM_BYTES>>>(
            k, v, kvp, nullptr, nullptr, nullptr, NNODES / SK, HID, HID, HID,
            (size_t)NNODES * HID, (size_t)(NNODES / SK) * HID,
            (size_t)NNODES * HID, (size_t)(NNODES / SK) * HID,
            (size_t)HID * HID, (size_t)NGRAPH * HID * HID, 0);
        kvs_reduce<<<(NGRAPH * HID * HID) / 256, 256>>>(kvp, kvs);
        // t = ((q @ kvs + N*v)/den + h)/2
        mm_tc<0,1,EPI_ATT,0,0><<<dim3(HID / BN, NNODES / BM, NGRAPH), 256, SMEM_BYTES>>>(
            q, kvs, t, v, h, den, HID, HID, HID, HID,
            0, 0, (size_t)HID * HID, 0, 0, 0, NNODES);
        ln_relu<<<row_blocks, 256>>>(t, dst, ln_g[l + 1], ln_b[l + 1], (l == 0) ? 1 : 0);
    }
}

// round 7
// speedup vs baseline: 1.9283x; 1.7760x over previous
#include <cuda_runtime.h>
#include <cuda_fp16.h>
#include <cstdint>
#include <cstddef>

// ---------------- problem constants ----------------
#define TOTAL    65536          // B_GRAPHS * N_NODES
#define NGRAPH   16
#define NNODES   4096
#define INCH     256
#define HID      512
#define LN_EPS   1e-5f
#define QK_EPS   1e-6f
#define SK       4              // split-K for kv GEMM
#define KBLOCKS  (TOTAL / 8)

// ---------------- GEMM tiling: 128x128 tile, warp 64x32, fp16 operands ----------------
#define BM 128
#define BN 128
#define BK 32
// TR0 slot: 128 rows x 40 halfs (80 B/row) = 10240 B
// TR1 slot: 32 rows x 136 halfs (272 B/row) = 8704 B
#define SLOT_BYTES  10240
#define STAGE_BYTES (2 * SLOT_BYTES)
#define NSTAGE 3
#define SMEM_BYTES (NSTAGE * STAGE_BYTES)   // 61440 -> 2 CTAs/SM

// epilogue modes
#define EPI_NONE 0
#define EPI_BIAS 1
#define EPI_ATT  2

// ---------------- scratch (device globals; no allocation) ----------------
__device__ __half g_h  [(size_t)TOTAL * HID];
__device__ __half g_q  [(size_t)TOTAL * HID];
__device__ __half g_k  [(size_t)TOTAL * HID];
__device__ __half g_v  [(size_t)TOTAL * HID];
__device__ __half g_xh [(size_t)TOTAL * INCH];
__device__ __half g_wh [(size_t)(HID * INCH + 6 * HID * HID)];
__device__ __half g_kvsh[(size_t)NGRAPH * HID * HID];
__device__ float  g_t  [(size_t)TOTAL * HID];
__device__ float  g_kvp [(size_t)SK * NGRAPH * HID * HID];
__device__ float  g_ksp [(size_t)KBLOCKS * HID];
__device__ float  g_ks  [(size_t)NGRAPH * HID];
__device__ float  g_den [(size_t)TOTAL];

// ---------------- helpers ----------------
__device__ __forceinline__ uint32_t smem_to_u32(const void* p) {
    uint32_t a;
    asm("{ .reg .u64 t; cvta.to.shared.u64 t, %1; cvt.u32.u64 %0, t; }" : "=r"(a) : "l"(p));
    return a;
}
__device__ __forceinline__ void mma_f16(float (&c)[4], const uint32_t (&a)[4],
                                        const uint32_t (&b)[2]) {
    asm volatile(
        "mma.sync.aligned.m16n8k16.row.col.f32.f16.f16.f32 "
        "{%0,%1,%2,%3}, {%4,%5,%6,%7}, {%8,%9}, {%0,%1,%2,%3};"
        : "+f"(c[0]), "+f"(c[1]), "+f"(c[2]), "+f"(c[3])
        : "r"(a[0]), "r"(a[1]), "r"(a[2]), "r"(a[3]), "r"(b[0]), "r"(b[1]));
}
__device__ __forceinline__ void ldsm_x4(uint32_t (&r)[4], uint32_t a) {
    asm volatile("ldmatrix.sync.aligned.m8n8.x4.shared.b16 {%0,%1,%2,%3}, [%4];"
        : "=r"(r[0]), "=r"(r[1]), "=r"(r[2]), "=r"(r[3]) : "r"(a));
}
__device__ __forceinline__ void ldsm_x4t(uint32_t (&r)[4], uint32_t a) {
    asm volatile("ldmatrix.sync.aligned.m8n8.x4.trans.shared.b16 {%0,%1,%2,%3}, [%4];"
        : "=r"(r[0]), "=r"(r[1]), "=r"(r[2]), "=r"(r[3]) : "r"(a));
}
__device__ __forceinline__ void cpa16(uint32_t dst, const void* src) {
    asm volatile("cp.async.cg.shared.global [%0], [%1], 16;" :: "r"(dst), "l"(src) : "memory");
}
#define CP_COMMIT() asm volatile("cp.async.commit_group;" ::: "memory")

// ================= fp16 mma.sync GEMM, 128x128 tile, 3-stage cp.async =================
// C[m0+i, n0+j] (+epilogue) = sum_k A(i,k) * B(j,k)
// TR==0: operand K-contiguous (slot S[row][k], 40-half stride, ldmatrix)
// TR==1: operand MN-contiguous (slot S[k][col], 136-half stride, ldmatrix.trans)
template <int TA, int TB, int EPI, int OUTH, int MULTI>
__global__ __launch_bounds__(256, 2)
void mm_tc(const __half* __restrict__ A, const __half* __restrict__ B,
           void* __restrict__ Cv, void* __restrict__ C1, void* __restrict__ C2,
           const __half* __restrict__ Vh, const __half* __restrict__ Hh,
           const float* __restrict__ Pf,
           int Kdim, int lda, int ldb, int ldc,
           size_t aG, size_t aS, size_t bG, size_t bS, size_t cG, size_t cS,
           int mZ) {
    extern __shared__ char smem[];
    const uint32_t sb = smem_to_u32(smem);

    const int tid = threadIdx.x;
    const int wid = tid >> 5, lane = tid & 31;
    const int wm = wid & 1, wn = wid >> 1;
    const int tr = lane >> 2, tq = lane & 3;

    const int z = blockIdx.z;
    const int graph = z & (NGRAPH - 1);
    const int split = z >> 4;
    A += aG * graph + aS * split;
    B += bG * graph + bS * split;
    void* Cp;
    int n0c;
    if (MULTI) {
        void* bufs[3] = { Cv, C1, C2 };
        Cp = bufs[blockIdx.x >> 2];
        n0c = (blockIdx.x & 3) * BN;
    } else {
        Cp = OUTH ? (void*)((__half*)Cv + cG * graph + cS * split)
                  : (void*)((float*)Cv + cG * graph + cS * split);
        n0c = blockIdx.x * BN;
    }
    const int m0 = blockIdx.y * BM + mZ * graph;
    const int n0 = blockIdx.x * BN;

    // per-lane fragment base offsets (bytes within slot)
    uint32_t aBase, bBase;
    if (TA == 0) aBase = (uint32_t)((wm * 64 + (lane & 15)) * 80 + (lane >> 4) * 16);
    else         aBase = (uint32_t)(((lane >> 4) * 8 + (lane & 7)) * 272
                                    + (wm * 64 + ((lane >> 3) & 1) * 8) * 2);
    if (TB == 0) bBase = (uint32_t)((wn * 32 + (lane >> 4) * 8 + (lane & 7)) * 80
                                    + ((lane >> 3) & 1) * 16);
    else         bBase = (uint32_t)((((lane >> 3) & 1) * 8 + (lane & 7)) * 272
                                    + (wn * 32 + (lane >> 4) * 8) * 2);

    // cp.async one pipeline stage (fp16 operands)
    auto issue = [&](int stage, int ktile) {
        const int k0 = ktile * BK;
        uint32_t slotA = sb + (uint32_t)stage * STAGE_BYTES;
        uint32_t slotB = slotA + SLOT_BYTES;
        if (TA == 0) {
            int row = tid >> 1, hb = (tid & 1) * 16;     // halfs
            const __half* s = A + (size_t)(m0 + row) * lda + k0 + hb;
            uint32_t d = slotA + (uint32_t)(row * 80 + hb * 2);
            cpa16(d, s); cpa16(d + 16, s + 8);
        } else {
            int kr = tid >> 3, c = (tid & 7) * 16;
            const __half* s = A + (size_t)(k0 + kr) * lda + m0 + c;
            uint32_t d = slotA + (uint32_t)(kr * 272 + c * 2);
            cpa16(d, s); cpa16(d + 16, s + 8);
        }
        if (TB == 0) {
            int row = tid >> 1, hb = (tid & 1) * 16;
            const __half* s = B + (size_t)(n0 + row) * ldb + k0 + hb;
            uint32_t d = slotB + (uint32_t)(row * 80 + hb * 2);
            cpa16(d, s); cpa16(d + 16, s + 8);
        } else {
            int kr = tid >> 3, c = (tid & 7) * 16;
            const __half* s = B + (size_t)(k0 + kr) * ldb + n0 + c;
            uint32_t d = slotB + (uint32_t)(kr * 272 + c * 2);
            cpa16(d, s); cpa16(d + 16, s + 8);
        }
    };

    float acc[4][4][4] = {};

    issue(0, 0); CP_COMMIT();
    issue(1, 1); CP_COMMIT();

    const int nK = Kdim / BK;
    for (int kt = 0; kt < nK; ++kt) {
        if (kt + 2 < nK) {
            issue((kt + 2) % NSTAGE, kt + 2); CP_COMMIT();
            asm volatile("cp.async.wait_group 2;" ::: "memory");
        } else if (kt + 1 < nK) {
            asm volatile("cp.async.wait_group 1;" ::: "memory");
        } else {
            asm volatile("cp.async.wait_group 0;" ::: "memory");
        }
        __syncthreads();

        uint32_t sA = sb + (uint32_t)(kt % NSTAGE) * STAGE_BYTES;
        uint32_t sB = sA + SLOT_BYTES;
#pragma unroll
        for (int ks = 0; ks < 2; ++ks) {          // two k16 steps per BK=32
            uint32_t afr[4][4], bfr[4][2];
            if (TA == 0) {
#pragma unroll
                for (int mi = 0; mi < 4; ++mi)
                    ldsm_x4(afr[mi], sA + aBase + (uint32_t)(mi * 1280 + ks * 32));
            } else {
#pragma unroll
                for (int mi = 0; mi < 4; ++mi)
                    ldsm_x4t(afr[mi], sA + aBase + (uint32_t)(mi * 32 + ks * 4352));
            }
            if (TB == 0) {
#pragma unroll
                for (int p = 0; p < 2; ++p) {
                    uint32_t t4[4];
                    ldsm_x4(t4, sB + bBase + (uint32_t)(p * 1280 + ks * 32));
                    bfr[2 * p + 0][0] = t4[0]; bfr[2 * p + 0][1] = t4[1];
                    bfr[2 * p + 1][0] = t4[2]; bfr[2 * p + 1][1] = t4[3];
                }
            } else {
#pragma unroll
                for (int p = 0; p < 2; ++p) {
                    uint32_t t4[4];
                    ldsm_x4t(t4, sB + bBase + (uint32_t)(p * 32 + ks * 4352));
                    bfr[2 * p + 0][0] = t4[0]; bfr[2 * p + 0][1] = t4[1];
                    bfr[2 * p + 1][0] = t4[2]; bfr[2 * p + 1][1] = t4[3];
                }
            }
#pragma unroll
            for (int mi = 0; mi < 4; ++mi)
#pragma unroll
                for (int ni = 0; ni < 4; ++ni)
                    mma_f16(acc[mi][ni], afr[mi], bfr[ni]);
        }
        __syncthreads();
    }

    // ---------------- epilogue ----------------
#pragma unroll
    for (int mi = 0; mi < 4; ++mi) {
        int rbase = m0 + wm * 64 + mi * 16 + tr;
#pragma unroll
        for (int half = 0; half < 2; ++half) {
            size_t row = (size_t)rbase + half * 8;
            float dinv = 0.0f;
            if (EPI == EPI_ATT) dinv = 1.0f / Pf[row];
#pragma unroll
            for (int ni = 0; ni < 4; ++ni) {
                int col = n0c + wn * 32 + ni * 8 + tq * 2;
                float c0 = acc[mi][ni][half * 2 + 0];
                float c1 = acc[mi][ni][half * 2 + 1];
                float2 o;
                if (EPI == EPI_NONE) {
                    o.x = c0; o.y = c1;
                } else if (EPI == EPI_BIAS) {
                    float2 bv = *(const float2*)(Pf + col);
                    o.x = c0 + bv.x; o.y = c1 + bv.y;
                } else {
                    float2 vv = __half22float2(*(const __half2*)(Vh + row * HID + col));
                    float2 hh = __half22float2(*(const __half2*)(Hh + row * HID + col));
                    o.x = ((c0 + 4096.0f * vv.x) * dinv + hh.x) * 0.5f;
                    o.y = ((c1 + 4096.0f * vv.y) * dinv + hh.y) * 0.5f;
                }
                if (OUTH) {
                    *(__half2*)((__half*)Cp + row * (size_t)ldc + col) =
                        __floats2half2_rn(o.x, o.y);
                } else {
                    *(float2*)((float*)Cp + row * (size_t)ldc + col) = o;
                }
            }
        }
    }
}

// ================= elementwise kernels =================
__device__ __forceinline__ float wred(float v) {
#pragma unroll
    for (int o = 16; o; o >>= 1) v += __shfl_xor_sync(0xffffffffu, v, o);
    return v;
}

__global__ void cvt_half(const float4* __restrict__ in, __half2* __restrict__ out, int n4) {
    int i = blockIdx.x * blockDim.x + threadIdx.x;
    if (i < n4) {
        float4 v = in[i];
        out[2 * i + 0] = __floats2half2_rn(v.x, v.y);
        out[2 * i + 1] = __floats2half2_rn(v.z, v.w);
    }
}

// LayerNorm + ReLU on fp32 input; OUT16 -> fp16 output, else fp32
template <int OUT16>
__global__ void ln_relu(const float* __restrict__ in, void* __restrict__ outv,
                        const float* __restrict__ g, const float* __restrict__ b) {
    size_t warp = ((size_t)blockIdx.x * blockDim.x + threadIdx.x) >> 5;
    int lane = threadIdx.x & 31;
    const float4* src = (const float4*)(in + warp * HID);
    float4 v[4];
    float s = 0.0f, s2 = 0.0f;
#pragma unroll
    for (int c = 0; c < 4; ++c) {
        v[c] = src[lane + 32 * c];
        s  += v[c].x + v[c].y + v[c].z + v[c].w;
        s2 += v[c].x * v[c].x + v[c].y * v[c].y + v[c].z * v[c].z + v[c].w * v[c].w;
    }
    s = wred(s); s2 = wred(s2);
    float mu = s * (1.0f / HID);
    float var = s2 * (1.0f / HID) - mu * mu;
    float rstd = rsqrtf(var + LN_EPS);
#pragma unroll
    for (int c = 0; c < 4; ++c) {
        int i4 = lane + 32 * c;
        float4 gg = ((const float4*)g)[i4];
        float4 bb = ((const float4*)b)[i4];
        float4 o;
        o.x = fmaxf(0.0f, (v[c].x - mu) * rstd * gg.x + bb.x);
        o.y = fmaxf(0.0f, (v[c].y - mu) * rstd * gg.y + bb.y);
        o.z = fmaxf(0.0f, (v[c].z - mu) * rstd * gg.z + bb.z);
        o.w = fmaxf(0.0f, (v[c].w - mu) * rstd * gg.w + bb.w);
        if (OUT16) {
            __half2* dst = (__half2*)((__half*)outv + warp * HID);
            dst[i4 * 2 + 0] = __floats2half2_rn(o.x, o.y);
            dst[i4 * 2 + 1] = __floats2half2_rn(o.z, o.w);
        } else {
            ((float4*)((float*)outv + warp * HID))[i4] = o;
        }
    }
}

// k (fp16): eps-substitute, L2-normalize, store fp16; 8-row column partials (fp32).
__global__ void norm_k(__half* __restrict__ X, float* __restrict__ Part) {
    __shared__ float sacc[8][HID];
    int w = threadIdx.x >> 5, lane = threadIdx.x & 31;
    size_t row = (size_t)blockIdx.x * 8 + w;
    __half2* p = (__half2*)(X + row * HID);
    float2 f[8];                                 // this lane's 16 values
    float s2 = 0.0f;
#pragma unroll
    for (int c = 0; c < 8; ++c) {
        f[c] = __half22float2(p[lane + 32 * c]);
        if (f[c].x == 0.0f) f[c].x = QK_EPS;
        if (f[c].y == 0.0f) f[c].y = QK_EPS;
        s2 += f[c].x * f[c].x + f[c].y * f[c].y;
    }
    s2 = wred(s2);
    float rn = rsqrtf(s2);
#pragma unroll
    for (int c = 0; c < 8; ++c) {
        f[c].x *= rn; f[c].y *= rn;
        __half2 h2 = __floats2half2_rn(f[c].x, f[c].y);
        p[lane + 32 * c] = h2;
        float2 fq = __half22float2(h2);          // accumulate what the GEMM will see
        sacc[w][(lane + 32 * c) * 2 + 0] = fq.x;
        sacc[w][(lane + 32 * c) * 2 + 1] = fq.y;
    }
    __syncthreads();
#pragma unroll
    for (int ch = threadIdx.x; ch < HID; ch += 256) {
        float sum = 0.0f;
#pragma unroll
        for (int r = 0; r < 8; ++r) sum += sacc[r][ch];
        Part[(size_t)blockIdx.x * HID + ch] = sum;
    }
}

__global__ void ksum_reduce(const float* __restrict__ Part, float* __restrict__ KS) {
    int idx = blockIdx.x * blockDim.x + threadIdx.x;    // 16*512
    int graph = idx >> 9, ch = idx & 511;
    float s = 0.0f;
    const float* p = Part + ((size_t)graph * 512) * HID + ch;
#pragma unroll 8
    for (int b = 0; b < 512; ++b) s += p[(size_t)b * HID];
    KS[idx] = s;
}

// q (fp16): eps-substitute, normalize, store fp16; den[row] = dot(qn, ks) + N
__global__ void norm_q_den(__half* __restrict__ X, const float* __restrict__ KS,
                           float* __restrict__ den) {
    size_t warp = ((size_t)blockIdx.x * blockDim.x + threadIdx.x) >> 5;
    int lane = threadIdx.x & 31;
    int graph = (int)(warp >> 12);
    __half2* p = (__half2*)(X + warp * HID);
    const float2* kp = (const float2*)(KS + (size_t)graph * HID);
    float2 f[8];
    float s2 = 0.0f;
#pragma unroll
    for (int c = 0; c < 8; ++c) {
        f[c] = __half22float2(p[lane + 32 * c]);
        if (f[c].x == 0.0f) f[c].x = QK_EPS;
        if (f[c].y == 0.0f) f[c].y = QK_EPS;
        s2 += f[c].x * f[c].x + f[c].y * f[c].y;
    }
    s2 = wred(s2);
    float rn = rsqrtf(s2);
    float d = 0.0f;
#pragma unroll
    for (int c = 0; c < 8; ++c) {
        f[c].x *= rn; f[c].y *= rn;
        __half2 h2 = __floats2half2_rn(f[c].x, f[c].y);
        p[lane + 32 * c] = h2;
        float2 fq = __half22float2(h2);
        float2 kk = kp[lane + 32 * c];
        d += fq.x * kk.x + fq.y * kk.y;
    }
    d = wred(d);
    if (lane == 0) den[warp] = d + (float)NNODES;
}

// kvs = sum of split-K partials (fp32) -> fp16
__global__ void kvs_reduce(const float* __restrict__ Part, __half2* __restrict__ KVS) {
    size_t o = (size_t)blockIdx.x * blockDim.x + threadIdx.x;   // pairs: 16*512*512/2
    size_t graph = o >> 17;
    size_t r = (o & ((1u << 17) - 1)) * 2;
    float s0 = 0.0f, s1 = 0.0f;
#pragma unroll
    for (int sp = 0; sp < SK; ++sp) {
        const float* p = Part + ((size_t)sp * NGRAPH + graph) * HID * HID + r;
        s0 += p[0]; s1 += p[1];
    }
    KVS[o] = __floats2half2_rn(s0, s1);
}

// ================= launch =================
extern "C" void kernel_launch(void* const* d_in, const int* in_sizes, int n_in,
                              void* d_out, int out_size) {
    const float* x     = (const float*)d_in[0];
    const float* fc0_w = (const float*)d_in[1];
    const float* fc0_b = (const float*)d_in[2];
    const float* ln_g[3] = { (const float*)d_in[3], (const float*)d_in[8],  (const float*)d_in[13] };
    const float* ln_b[3] = { (const float*)d_in[4], (const float*)d_in[9],  (const float*)d_in[14] };
    const float* qw[2] = { (const float*)d_in[5],  (const float*)d_in[10] };
    const float* kw[2] = { (const float*)d_in[6],  (const float*)d_in[11] };
    const float* vw[2] = { (const float*)d_in[7],  (const float*)d_in[12] };
    float* out = (float*)d_out;
    // batch = repeat(arange(16), 4096): argsort and rev_perm are identities.

    __half *h, *q, *k, *v, *xh, *wh, *kvsh;
    float *t, *kvp, *ksp, *ks, *den;
    cudaGetSymbolAddress((void**)&h,    g_h);
    cudaGetSymbolAddress((void**)&q,    g_q);
    cudaGetSymbolAddress((void**)&k,    g_k);
    cudaGetSymbolAddress((void**)&v,    g_v);
    cudaGetSymbolAddress((void**)&xh,   g_xh);
    cudaGetSymbolAddress((void**)&wh,   g_wh);
    cudaGetSymbolAddress((void**)&kvsh, g_kvsh);
    cudaGetSymbolAddress((void**)&t,    g_t);
    cudaGetSymbolAddress((void**)&kvp,  g_kvp);
    cudaGetSymbolAddress((void**)&ksp,  g_ksp);
    cudaGetSymbolAddress((void**)&ks,   g_ks);
    cudaGetSymbolAddress((void**)&den,  g_den);

    cudaFuncSetAttribute((const void*)mm_tc<0,0,EPI_BIAS,0,0>,
                         cudaFuncAttributeMaxDynamicSharedMemorySize, SMEM_BYTES);
    cudaFuncSetAttribute((const void*)mm_tc<0,0,EPI_NONE,1,1>,
                         cudaFuncAttributeMaxDynamicSharedMemorySize, SMEM_BYTES);
    cudaFuncSetAttribute((const void*)mm_tc<1,1,EPI_NONE,0,0>,
                         cudaFuncAttributeMaxDynamicSharedMemorySize, SMEM_BYTES);
    cudaFuncSetAttribute((const void*)mm_tc<0,1,EPI_ATT,0,0>,
                         cudaFuncAttributeMaxDynamicSharedMemorySize, SMEM_BYTES);

    // fp16 weights: fc0 then per-layer [3*HID, HID] contiguous (q,k,v)
    __half* wh_fc0 = wh;
    __half* wh_l[2] = { wh + (size_t)HID * INCH,
                        wh + (size_t)HID * INCH + 3 * (size_t)HID * HID };

    cvt_half<<<(TOTAL * INCH / 4 + 255) / 256, 256>>>((const float4*)x, (__half2*)xh, TOTAL * INCH / 4);
    cvt_half<<<(HID * INCH / 4 + 255) / 256, 256>>>((const float4*)fc0_w, (__half2*)wh_fc0, HID * INCH / 4);
    const float* wsrc[2][3] = { { qw[0], kw[0], vw[0] }, { qw[1], kw[1], vw[1] } };
    for (int l = 0; l < 2; ++l)
        for (int j = 0; j < 3; ++j)
            cvt_half<<<(HID * HID / 4 + 255) / 256, 256>>>(
                (const float4*)wsrc[l][j], (__half2*)(wh_l[l] + (size_t)j * HID * HID), HID * HID / 4);

    const int row_blocks = TOTAL / 8;

    // t = x @ fc0_w^T + b ; h = fp16(relu(LN(t)))
    mm_tc<0,0,EPI_BIAS,0,0><<<dim3(HID / BN, TOTAL / BM), 256, SMEM_BYTES>>>(
        xh, wh_fc0, t, nullptr, nullptr, nullptr, nullptr, fc0_b,
        INCH, INCH, INCH, HID, 0, 0, 0, 0, 0, 0, 0);
    ln_relu<1><<<row_blocks, 256>>>(t, h, ln_g[0], ln_b[0]);

    for (int l = 0; l < 2; ++l) {
        // merged QKV: B = [1536,512] fp16 weights; outputs q/k/v fp16
        mm_tc<0,0,EPI_NONE,1,1><<<dim3(12, TOTAL / BM), 256, SMEM_BYTES>>>(
            h, wh_l[l], q, k, v, nullptr, nullptr, nullptr,
            HID, HID, HID, HID, 0, 0, 0, 0, 0, 0, 0);
        norm_k<<<KBLOCKS, 256>>>(k, ksp);
        ksum_reduce<<<(NGRAPH * HID) / 256, 256>>>(ksp, ks);
        norm_q_den<<<row_blocks, 256>>>(q, ks, den);
        // kvp[split][g][m,d] = sum_{n in split} k[g,n,m] * v[g,n,d]
        mm_tc<1,1,EPI_NONE,0,0><<<dim3(HID / BN, HID / BM, NGRAPH * SK), 256, SMEM_BYTES>>>(
            k, v, kvp, nullptr, nullptr, nullptr, nullptr, nullptr,
            NNODES / SK, HID, HID, HID,
            (size_t)NNODES * HID, (size_t)(NNODES / SK) * HID,
            (size_t)NNODES * HID, (size_t)(NNODES / SK) * HID,
            (size_t)HID * HID, (size_t)NGRAPH * HID * HID, 0);
        kvs_reduce<<<(NGRAPH * HID * HID / 2) / 256, 256>>>(kvp, (__half2*)kvsh);
        // t = ((q @ kvs + N*v)/den + h)/2
        mm_tc<0,1,EPI_ATT,0,0><<<dim3(HID / BN, NNODES / BM, NGRAPH), 256, SMEM_BYTES>>>(
            q, kvsh, t, nullptr, nullptr, v, h, den,
            HID, HID, HID, HID,
            0, 0, (size_t)HID * HID, 0, 0, 0, NNODES);
        if (l == 0) ln_relu<1><<<row_blocks, 256>>>(t, h, ln_g[1], ln_b[1]);
        else        ln_relu<0><<<row_blocks, 256>>>(t, out, ln_g[2], ln_b[2]);
    }
}